// round 6
// baseline (speedup 1.0000x reference)
#include <cuda_runtime.h>
#include <cuda_bf16.h>
#include <mma.h>
#include <cstdint>

#define N_NODES 100000
#define N_PAD   100096        // padded to 128-row tile multiple
#define N_EDGES 1600000
#define D 128
#define SCAN_B 1024
#define N_SCAN_BLOCKS ((N_NODES + SCAN_B - 1) / SCAN_B)   // 98

using namespace nvcuda;

// Scratch (allocation-free rule: __device__ globals). Row-padded so boundary
// wmma tiles can store unguarded.
__device__ float g_h[(size_t)N_PAD * D];
__device__ float g_x[(size_t)N_PAD * D];   // pad rows stay 0 forever
__device__ float g_dinv[N_NODES];
__device__ int   g_is64;
__device__ int   g_erow[N_EDGES];
__device__ int   g_ecol[N_EDGES];
__device__ int   g_cnt[N_NODES];
__device__ int   g_rowptr[N_NODES + 1];
__device__ int   g_cursor[N_NODES];
__device__ int   g_src[N_EDGES];
__device__ int   g_bsum[N_SCAN_BLOCKS];

// ===========================================================================
// Edge decode + CSR build (unchanged from R4 — proven)
// ===========================================================================
__global__ void k_detect(const unsigned int* __restrict__ buf) {
    __shared__ unsigned int acc;
    if (threadIdx.x == 0) acc = 0u;
    __syncthreads();
    unsigned int local = 0u;
    for (int i = threadIdx.x; i < 4096; i += blockDim.x)
        local |= buf[2 * i + 1];
    atomicOr(&acc, local);
    __syncthreads();
    if (threadIdx.x == 0) g_is64 = (acc == 0u) ? 1 : 0;
}

__global__ void k_convert(const void* __restrict__ buf) {
    int e = blockIdx.x * blockDim.x + threadIdx.x;
    if (e >= N_EDGES) return;
    if (g_is64) {
        const long long* p = (const long long*)buf;
        g_erow[e] = (int)p[e];
        g_ecol[e] = (int)p[e + N_EDGES];
    } else {
        const int* p = (const int*)buf;
        g_erow[e] = p[e];
        g_ecol[e] = p[e + N_EDGES];
    }
}

__global__ void k_zero() {
    int i = blockIdx.x * blockDim.x + threadIdx.x;
    if (i < N_NODES) { g_cnt[i] = 0; g_cursor[i] = 0; }
}

__global__ void k_hist() {
    int e = blockIdx.x * blockDim.x + threadIdx.x;
    if (e < N_EDGES) atomicAdd(&g_cnt[g_ecol[e]], 1);
}

__global__ void k_dinv() {
    int i = blockIdx.x * blockDim.x + threadIdx.x;
    if (i < N_NODES) g_dinv[i] = rsqrtf(1.0f + (float)g_cnt[i]);
}

__global__ void __launch_bounds__(SCAN_B)
k_scan1() {
    __shared__ int s[SCAN_B];
    int i = blockIdx.x * SCAN_B + threadIdx.x;
    int v = (i < N_NODES) ? g_cnt[i] : 0;
    s[threadIdx.x] = v;
    __syncthreads();
#pragma unroll
    for (int off = 1; off < SCAN_B; off <<= 1) {
        int t = (threadIdx.x >= off) ? s[threadIdx.x - off] : 0;
        __syncthreads();
        s[threadIdx.x] += t;
        __syncthreads();
    }
    if (i < N_NODES) g_rowptr[i] = s[threadIdx.x] - v;
    if (threadIdx.x == SCAN_B - 1) g_bsum[blockIdx.x] = s[SCAN_B - 1];
}

__global__ void k_scan2() {
    if (threadIdx.x == 0) {
        int run = 0;
        for (int b = 0; b < N_SCAN_BLOCKS; b++) {
            int t = g_bsum[b];
            g_bsum[b] = run;
            run += t;
        }
        g_rowptr[N_NODES] = N_EDGES;
    }
}

__global__ void k_scan3() {
    int i = blockIdx.x * blockDim.x + threadIdx.x;
    if (i < N_NODES) g_rowptr[i] += g_bsum[i / SCAN_B];
}

__global__ void k_fill() {
    int e = blockIdx.x * blockDim.x + threadIdx.x;
    if (e >= N_EDGES) return;
    int c = g_ecol[e];
    int pos = atomicAdd(&g_cursor[c], 1);
    g_src[g_rowptr[c] + pos] = g_erow[e];
}

// ===========================================================================
// Tensor-core GEMM via wmma bf16 split precision (3 accumulating terms).
// g_h[tile 128 x 128] = A @ W,  A fp32 -> (hi+lo) bf16, W fp32 -> (hi+lo).
// 256 threads = 8 warps in 4(M) x 2(N); warp tile 32x64 = 2x4 wmma frags.
// Smem planes padded to LDM=136 (272B stride -> conflict-free ldmatrix).
// ===========================================================================
#define LDM 136
#define PLANE (128 * LDM)                       // elements per bf16 plane
#define SMEM_BYTES (4 * PLANE * sizeof(__nv_bfloat16))   // 139264 B

template<bool FROM_GX>
__global__ void __launch_bounds__(256, 1)
k_gemm_wmma(const float* __restrict__ Ain, const float* __restrict__ W) {
    extern __shared__ __nv_bfloat16 smem[];
    __nv_bfloat16* As_hi = smem;
    __nv_bfloat16* As_lo = smem + PLANE;
    __nv_bfloat16* Ws_hi = smem + 2 * PLANE;
    __nv_bfloat16* Ws_lo = smem + 3 * PLANE;

    const int tid = threadIdx.x;
    const int wid = tid >> 5;
    const int wm = wid & 3;        // M quadrant (32 rows)
    const int wn = wid >> 2;       // N half (64 cols)
    const int row0 = blockIdx.x * 128;
    const float* A = FROM_GX ? g_x : Ain;

    // ---- Convert A tile and W into hi/lo bf16 smem planes (float4 loads)
    const float4* A4 = (const float4*)A;
    const float4* W4 = (const float4*)W;
    for (int idx = tid; idx < 4096; idx += 256) {   // 128 rows x 32 float4
        int r = idx >> 5, c4 = idx & 31;
        // W (always in-bounds)
        {
            float4 v = W4[r * 32 + c4];
            float xs[4] = {v.x, v.y, v.z, v.w};
#pragma unroll
            for (int p = 0; p < 4; p++) {
                __nv_bfloat16 h = __float2bfloat16(xs[p]);
                __nv_bfloat16 l = __float2bfloat16(xs[p] - __bfloat162float(h));
                Ws_hi[r * LDM + c4 * 4 + p] = h;
                Ws_lo[r * LDM + c4 * 4 + p] = l;
            }
        }
        // A (guard rows >= N_NODES)
        {
            int row = row0 + r;
            float4 v = (row < N_NODES) ? A4[(size_t)row * 32 + c4]
                                       : make_float4(0.f, 0.f, 0.f, 0.f);
            float xs[4] = {v.x, v.y, v.z, v.w};
#pragma unroll
            for (int p = 0; p < 4; p++) {
                __nv_bfloat16 h = __float2bfloat16(xs[p]);
                __nv_bfloat16 l = __float2bfloat16(xs[p] - __bfloat162float(h));
                As_hi[r * LDM + c4 * 4 + p] = h;
                As_lo[r * LDM + c4 * 4 + p] = l;
            }
        }
    }
    __syncthreads();

    // ---- MMA mainloop
    wmma::fragment<wmma::accumulator, 16, 16, 16, float> c[2][4];
#pragma unroll
    for (int i = 0; i < 2; i++)
#pragma unroll
        for (int j = 0; j < 4; j++) wmma::fill_fragment(c[i][j], 0.0f);

#pragma unroll
    for (int k = 0; k < 8; k++) {
        wmma::fragment<wmma::matrix_a, 16, 16, 16, __nv_bfloat16, wmma::row_major> ah[2], al[2];
        wmma::fragment<wmma::matrix_b, 16, 16, 16, __nv_bfloat16, wmma::row_major> bh[4], bl[4];
#pragma unroll
        for (int i = 0; i < 2; i++) {
            const int ar = wm * 32 + i * 16;
            wmma::load_matrix_sync(ah[i], As_hi + ar * LDM + k * 16, LDM);
            wmma::load_matrix_sync(al[i], As_lo + ar * LDM + k * 16, LDM);
        }
#pragma unroll
        for (int j = 0; j < 4; j++) {
            const int bc = wn * 64 + j * 16;
            wmma::load_matrix_sync(bh[j], Ws_hi + (k * 16) * LDM + bc, LDM);
            wmma::load_matrix_sync(bl[j], Ws_lo + (k * 16) * LDM + bc, LDM);
        }
#pragma unroll
        for (int i = 0; i < 2; i++)
#pragma unroll
            for (int j = 0; j < 4; j++) {
                wmma::mma_sync(c[i][j], ah[i], bh[j], c[i][j]);
                wmma::mma_sync(c[i][j], ah[i], bl[j], c[i][j]);
                wmma::mma_sync(c[i][j], al[i], bh[j], c[i][j]);
            }
    }

    // ---- Store to g_h (row-padded to N_PAD: unguarded tile stores are safe)
#pragma unroll
    for (int i = 0; i < 2; i++)
#pragma unroll
        for (int j = 0; j < 4; j++) {
            int row = row0 + wm * 32 + i * 16;
            int col = wn * 64 + j * 16;
            wmma::store_matrix_sync(g_h + (size_t)row * D + col, c[i][j], D,
                                    wmma::mem_row_major);
        }
}

// ===========================================================================
// Aggregation (gather, no atomics): one warp per target node (unchanged)
// ===========================================================================
__global__ void __launch_bounds__(256)
k_aggregate(const float* __restrict__ bias, float* __restrict__ out,
            int use_out) {
    int node = (blockIdx.x * blockDim.x + threadIdx.x) >> 5;
    int lane = threadIdx.x & 31;
    if (node >= N_NODES) return;

    float* dst = use_out ? out : g_x;
    float dinv_c = g_dinv[node];
    float s = dinv_c * dinv_c;

    float4 bb = ((const float4*)bias)[lane];
    float4 hself = ((const float4*)(g_h + (size_t)node * D))[lane];
    float4 acc = make_float4(fmaf(hself.x, s, bb.x), fmaf(hself.y, s, bb.y),
                             fmaf(hself.z, s, bb.z), fmaf(hself.w, s, bb.w));

    int beg = g_rowptr[node];
    int end = g_rowptr[node + 1];
    for (int base = beg; base < end; base += 32) {
        int j = base + lane;
        int r = 0;
        float dr = 0.0f;
        if (j < end) {
            r = g_src[j];
            dr = g_dinv[r];
        }
        int cnt = min(32, end - base);
        for (int k = 0; k < cnt; k++) {
            int rr = __shfl_sync(0xffffffffu, r, k);
            float nn = __shfl_sync(0xffffffffu, dr, k) * dinv_c;
            float4 hv = ((const float4*)(g_h + (size_t)rr * D))[lane];
            acc.x = fmaf(hv.x, nn, acc.x);
            acc.y = fmaf(hv.y, nn, acc.y);
            acc.z = fmaf(hv.z, nn, acc.z);
            acc.w = fmaf(hv.w, nn, acc.w);
        }
    }

    acc.x = fmaxf(acc.x, 0.f); acc.y = fmaxf(acc.y, 0.f);
    acc.z = fmaxf(acc.z, 0.f); acc.w = fmaxf(acc.w, 0.f);
    ((float4*)(dst + (size_t)node * D))[lane] = acc;
}

// ===========================================================================
// Launch
// ===========================================================================
extern "C" void kernel_launch(void* const* d_in, const int* in_sizes, int n_in,
                              void* d_out, int out_size) {
    const void* edge = d_in[0];
    const float* emb = (const float*)d_in[1];
    const float* Ws  = (const float*)d_in[2];
    const float* bs  = (const float*)d_in[3];
    float* out = (float*)d_out;

    // Opt in to >48KB dynamic smem (idempotent; not an allocation)
    static bool attr_done = false;
    if (!attr_done) {
        cudaFuncSetAttribute(k_gemm_wmma<false>,
                             cudaFuncAttributeMaxDynamicSharedMemorySize, SMEM_BYTES);
        cudaFuncSetAttribute(k_gemm_wmma<true>,
                             cudaFuncAttributeMaxDynamicSharedMemorySize, SMEM_BYTES);
        attr_done = true;
    }

    const int nb_nodes = (N_NODES + 255) / 256;
    const int nb_edges = (N_EDGES + 255) / 256;

    k_detect<<<1, 256>>>((const unsigned int*)edge);
    k_convert<<<nb_edges, 256>>>(edge);
    k_zero<<<nb_nodes, 256>>>();
    k_hist<<<nb_edges, 256>>>();
    k_dinv<<<nb_nodes, 256>>>();
    k_scan1<<<N_SCAN_BLOCKS, SCAN_B>>>();
    k_scan2<<<1, 32>>>();
    k_scan3<<<nb_nodes, 256>>>();
    k_fill<<<nb_edges, 256>>>();

    const int gemm_blocks = N_PAD / 128;                 // 782
    const int agg_blocks = (N_NODES * 32 + 255) / 256;

    // Layer 0
    k_gemm_wmma<false><<<gemm_blocks, 256, SMEM_BYTES>>>(emb, Ws + 0 * D * D);
    k_aggregate<<<agg_blocks, 256>>>(bs + 0 * D, out, 0);
    // Layer 1
    k_gemm_wmma<true><<<gemm_blocks, 256, SMEM_BYTES>>>(nullptr, Ws + 1 * D * D);
    k_aggregate<<<agg_blocks, 256>>>(bs + 1 * D, out, 0);
    // Layer 2 -> d_out (ReLU in aggregate)
    k_gemm_wmma<true><<<gemm_blocks, 256, SMEM_BYTES>>>(nullptr, Ws + 2 * D * D);
    k_aggregate<<<agg_blocks, 256>>>(bs + 2 * D, out, 1);
}

// round 7
// speedup vs baseline: 1.1082x; 1.1082x over previous
#include <cuda_runtime.h>
#include <cuda_bf16.h>
#include <mma.h>
#include <cstdint>

#define N_NODES 100000
#define N_PAD   100096        // multiple of 64-row tiles (and 128)
#define N_EDGES 1600000
#define D 128
#define SCAN_B 1024
#define N_SCAN_BLOCKS ((N_NODES + SCAN_B - 1) / SCAN_B)   // 98

using namespace nvcuda;

// Scratch (allocation-free rule: __device__ globals). Row-padded so boundary
// wmma tile stores stay in bounds; pad rows of g_x stay zero forever.
__device__ float g_h[(size_t)N_PAD * D];
__device__ float g_x[(size_t)N_PAD * D];
__device__ float g_dinv[N_NODES];
__device__ int   g_is64;
__device__ int   g_erow[N_EDGES];
__device__ int   g_ecol[N_EDGES];
__device__ int   g_cnt[N_NODES];
__device__ int   g_rowptr[N_NODES + 1];
__device__ int   g_cursor[N_NODES];
__device__ int   g_src[N_EDGES];
__device__ int   g_bsum[N_SCAN_BLOCKS];

// ===========================================================================
// Setup: decode, degree histogram, scan, CSR fill (trimmed to 7 launches)
// ===========================================================================
__global__ void k_detect(const unsigned int* __restrict__ buf) {
    __shared__ unsigned int acc;
    if (threadIdx.x == 0) acc = 0u;
    __syncthreads();
    unsigned int local = 0u;
    for (int i = threadIdx.x; i < 4096; i += blockDim.x)
        local |= buf[2 * i + 1];
    atomicOr(&acc, local);
    __syncthreads();
    if (threadIdx.x == 0) g_is64 = (acc == 0u) ? 1 : 0;
}

__global__ void k_zero() {
    int i = blockIdx.x * blockDim.x + threadIdx.x;
    if (i < N_NODES) { g_cnt[i] = 0; g_cursor[i] = 0; }
}

// decode both rows AND build the in-degree histogram in one pass
__global__ void k_convert_hist(const void* __restrict__ buf) {
    int e = blockIdx.x * blockDim.x + threadIdx.x;
    if (e >= N_EDGES) return;
    int r, c;
    if (g_is64) {
        const long long* p = (const long long*)buf;
        r = (int)p[e];
        c = (int)p[e + N_EDGES];
    } else {
        const int* p = (const int*)buf;
        r = p[e];
        c = p[e + N_EDGES];
    }
    g_erow[e] = r;
    g_ecol[e] = c;
    atomicAdd(&g_cnt[c], 1);
}

// block-level exclusive scan of degrees; also computes dinv = rsqrt(1+deg)
__global__ void __launch_bounds__(SCAN_B)
k_scan1() {
    __shared__ int s[SCAN_B];
    int i = blockIdx.x * SCAN_B + threadIdx.x;
    int v = (i < N_NODES) ? g_cnt[i] : 0;
    if (i < N_NODES) g_dinv[i] = rsqrtf(1.0f + (float)v);
    s[threadIdx.x] = v;
    __syncthreads();
#pragma unroll
    for (int off = 1; off < SCAN_B; off <<= 1) {
        int t = (threadIdx.x >= off) ? s[threadIdx.x - off] : 0;
        __syncthreads();
        s[threadIdx.x] += t;
        __syncthreads();
    }
    if (i < N_NODES) g_rowptr[i] = s[threadIdx.x] - v;
    if (threadIdx.x == SCAN_B - 1) g_bsum[blockIdx.x] = s[SCAN_B - 1];
}

// parallel scan of the 98 block sums (was a 1-thread serial loop: ~25us)
__global__ void k_scan2() {
    __shared__ int s[128];
    int t = threadIdx.x;
    int v = (t < N_SCAN_BLOCKS) ? g_bsum[t] : 0;
    s[t] = v;
    __syncthreads();
#pragma unroll
    for (int off = 1; off < 128; off <<= 1) {
        int tv = (t >= off) ? s[t - off] : 0;
        __syncthreads();
        s[t] += tv;
        __syncthreads();
    }
    if (t < N_SCAN_BLOCKS) g_bsum[t] = s[t] - v;   // exclusive
    if (t == 0) g_rowptr[N_NODES] = N_EDGES;
}

__global__ void k_scan3() {
    int i = blockIdx.x * blockDim.x + threadIdx.x;
    if (i < N_NODES) g_rowptr[i] += g_bsum[i / SCAN_B];
}

__global__ void k_fill() {
    int e = blockIdx.x * blockDim.x + threadIdx.x;
    if (e >= N_EDGES) return;
    int c = g_ecol[e];
    int pos = atomicAdd(&g_cursor[c], 1);
    g_src[g_rowptr[c] + pos] = g_erow[e];
}

// ===========================================================================
// GEMM via single-pass TF32 wmma: g_h[64-row tile] = A @ W.
// 256 threads = 8 warps (2 M x 4 N), warp tile 32x32 = 2x2 m16n16k8 frags.
// Smem: A 64x136 + W 128x136 fp32 (tf32-rounded at copy) = 104.4 KB -> occ 2.
// All copies are float4; mainloop is pure load_matrix_sync + mma_sync.
// ===========================================================================
#define LDMF 136
#define GEMM_SMEM ((64 + 128) * LDMF * 4)   // 104448 B

template<bool FROM_GX>
__global__ void __launch_bounds__(256, 2)
k_gemm_tf32(const float* __restrict__ Ain, const float* __restrict__ W) {
    extern __shared__ float sm[];
    float* As = sm;                 // [64][LDMF]
    float* Bs = sm + 64 * LDMF;     // [128][LDMF]

    const int tid = threadIdx.x;
    const int wid = tid >> 5;
    const int wm = wid >> 2;        // 0-1: 32-row strip
    const int wn = wid & 3;         // 0-3: 32-col strip
    const int row0 = blockIdx.x * 64;
    const float* A = FROM_GX ? g_x : Ain;

    const float4* A4 = (const float4*)A;
    const float4* W4 = (const float4*)W;

    // W: 128 rows x 32 float4 = 4096, 16 per thread
    for (int idx = tid; idx < 4096; idx += 256) {
        int r = idx >> 5, c4 = idx & 31;
        float4 v = W4[r * 32 + c4];
        float* dst = Bs + r * LDMF + c4 * 4;
        dst[0] = wmma::__float_to_tf32(v.x);
        dst[1] = wmma::__float_to_tf32(v.y);
        dst[2] = wmma::__float_to_tf32(v.z);
        dst[3] = wmma::__float_to_tf32(v.w);
    }
    // A tile: 64 rows x 32 float4 = 2048, 8 per thread
    for (int idx = tid; idx < 2048; idx += 256) {
        int r = idx >> 5, c4 = idx & 31;
        int row = row0 + r;
        float4 v = (row < N_NODES) ? A4[(size_t)row * 32 + c4]
                                   : make_float4(0.f, 0.f, 0.f, 0.f);
        float* dst = As + r * LDMF + c4 * 4;
        dst[0] = wmma::__float_to_tf32(v.x);
        dst[1] = wmma::__float_to_tf32(v.y);
        dst[2] = wmma::__float_to_tf32(v.z);
        dst[3] = wmma::__float_to_tf32(v.w);
    }
    __syncthreads();

    wmma::fragment<wmma::accumulator, 16, 16, 8, float> c[2][2];
#pragma unroll
    for (int i = 0; i < 2; i++)
#pragma unroll
        for (int j = 0; j < 2; j++) wmma::fill_fragment(c[i][j], 0.0f);

#pragma unroll
    for (int k = 0; k < 16; k++) {
        wmma::fragment<wmma::matrix_a, 16, 16, 8, wmma::precision::tf32,
                       wmma::row_major> a[2];
        wmma::fragment<wmma::matrix_b, 16, 16, 8, wmma::precision::tf32,
                       wmma::row_major> b[2];
#pragma unroll
        for (int i = 0; i < 2; i++)
            wmma::load_matrix_sync(a[i], As + (wm * 32 + i * 16) * LDMF + k * 8,
                                   LDMF);
#pragma unroll
        for (int j = 0; j < 2; j++)
            wmma::load_matrix_sync(b[j], Bs + (k * 8) * LDMF + wn * 32 + j * 16,
                                   LDMF);
#pragma unroll
        for (int i = 0; i < 2; i++)
#pragma unroll
            for (int j = 0; j < 2; j++)
                wmma::mma_sync(c[i][j], a[i], b[j], c[i][j]);
    }

#pragma unroll
    for (int i = 0; i < 2; i++)
#pragma unroll
        for (int j = 0; j < 2; j++) {
            int row = row0 + wm * 32 + i * 16;
            int col = wn * 32 + j * 16;
            wmma::store_matrix_sync(g_h + (size_t)row * D + col, c[i][j], D,
                                    wmma::mem_row_major);
        }
}

// ===========================================================================
// Aggregation (gather, no atomics): one warp per target node.
// 2-edge unroll with dual accumulators: halves the FMA chain, doubles MLP.
// ===========================================================================
__global__ void __launch_bounds__(256)
k_aggregate(const float* __restrict__ bias, float* __restrict__ out,
            int use_out) {
    int node = (blockIdx.x * blockDim.x + threadIdx.x) >> 5;
    int lane = threadIdx.x & 31;
    if (node >= N_NODES) return;

    float* dst = use_out ? out : g_x;
    float dinv_c = g_dinv[node];
    float s = dinv_c * dinv_c;

    float4 bb = ((const float4*)bias)[lane];
    float4 hself = ((const float4*)(g_h + (size_t)node * D))[lane];
    float4 acc0 = make_float4(fmaf(hself.x, s, bb.x), fmaf(hself.y, s, bb.y),
                              fmaf(hself.z, s, bb.z), fmaf(hself.w, s, bb.w));
    float4 acc1 = make_float4(0.f, 0.f, 0.f, 0.f);

    int beg = g_rowptr[node];
    int end = g_rowptr[node + 1];
    for (int base = beg; base < end; base += 32) {
        int j = base + lane;
        int r = 0;
        float nn = 0.0f;
        if (j < end) {
            r = g_src[j];
            nn = g_dinv[r] * dinv_c;
        }
        int cnt = min(32, end - base);
        int k = 0;
        for (; k + 1 < cnt; k += 2) {
            int rr0 = __shfl_sync(0xffffffffu, r, k);
            float n0 = __shfl_sync(0xffffffffu, nn, k);
            int rr1 = __shfl_sync(0xffffffffu, r, k + 1);
            float n1 = __shfl_sync(0xffffffffu, nn, k + 1);
            float4 h0 = ((const float4*)(g_h + (size_t)rr0 * D))[lane];
            float4 h1 = ((const float4*)(g_h + (size_t)rr1 * D))[lane];
            acc0.x = fmaf(h0.x, n0, acc0.x); acc1.x = fmaf(h1.x, n1, acc1.x);
            acc0.y = fmaf(h0.y, n0, acc0.y); acc1.y = fmaf(h1.y, n1, acc1.y);
            acc0.z = fmaf(h0.z, n0, acc0.z); acc1.z = fmaf(h1.z, n1, acc1.z);
            acc0.w = fmaf(h0.w, n0, acc0.w); acc1.w = fmaf(h1.w, n1, acc1.w);
        }
        if (k < cnt) {
            int rr0 = __shfl_sync(0xffffffffu, r, k);
            float n0 = __shfl_sync(0xffffffffu, nn, k);
            float4 h0 = ((const float4*)(g_h + (size_t)rr0 * D))[lane];
            acc0.x = fmaf(h0.x, n0, acc0.x);
            acc0.y = fmaf(h0.y, n0, acc0.y);
            acc0.z = fmaf(h0.z, n0, acc0.z);
            acc0.w = fmaf(h0.w, n0, acc0.w);
        }
    }

    float4 acc = make_float4(acc0.x + acc1.x, acc0.y + acc1.y,
                             acc0.z + acc1.z, acc0.w + acc1.w);
    acc.x = fmaxf(acc.x, 0.f); acc.y = fmaxf(acc.y, 0.f);
    acc.z = fmaxf(acc.z, 0.f); acc.w = fmaxf(acc.w, 0.f);
    ((float4*)(dst + (size_t)node * D))[lane] = acc;
}

// ===========================================================================
// Launch
// ===========================================================================
extern "C" void kernel_launch(void* const* d_in, const int* in_sizes, int n_in,
                              void* d_out, int out_size) {
    const void* edge = d_in[0];
    const float* emb = (const float*)d_in[1];
    const float* Ws  = (const float*)d_in[2];
    const float* bs  = (const float*)d_in[3];
    float* out = (float*)d_out;

    static bool attr_done = false;
    if (!attr_done) {
        cudaFuncSetAttribute(k_gemm_tf32<false>,
                             cudaFuncAttributeMaxDynamicSharedMemorySize, GEMM_SMEM);
        cudaFuncSetAttribute(k_gemm_tf32<true>,
                             cudaFuncAttributeMaxDynamicSharedMemorySize, GEMM_SMEM);
        attr_done = true;
    }

    const int nb_nodes = (N_NODES + 255) / 256;
    const int nb_edges = (N_EDGES + 255) / 256;

    k_detect<<<1, 256>>>((const unsigned int*)edge);
    k_zero<<<nb_nodes, 256>>>();
    k_convert_hist<<<nb_edges, 256>>>(edge);
    k_scan1<<<N_SCAN_BLOCKS, SCAN_B>>>();
    k_scan2<<<1, 128>>>();
    k_scan3<<<nb_nodes, 256>>>();
    k_fill<<<nb_edges, 256>>>();

    const int gemm_blocks = N_PAD / 64;                  // 1564
    const int agg_blocks = (N_NODES * 32 + 255) / 256;   // 12500

    // Layer 0
    k_gemm_tf32<false><<<gemm_blocks, 256, GEMM_SMEM>>>(emb, Ws + 0 * D * D);
    k_aggregate<<<agg_blocks, 256>>>(bs + 0 * D, out, 0);
    // Layer 1
    k_gemm_tf32<true><<<gemm_blocks, 256, GEMM_SMEM>>>(nullptr, Ws + 1 * D * D);
    k_aggregate<<<agg_blocks, 256>>>(bs + 1 * D, out, 0);
    // Layer 2 -> d_out (ReLU in aggregate)
    k_gemm_tf32<true><<<gemm_blocks, 256, GEMM_SMEM>>>(nullptr, Ws + 2 * D * D);
    k_aggregate<<<agg_blocks, 256>>>(bs + 2 * D, out, 1);
}

// round 8
// speedup vs baseline: 1.1778x; 1.0628x over previous
#include <cuda_runtime.h>
#include <cuda_fp16.h>
#include <mma.h>
#include <cstdint>

#define N_NODES 100000
#define N_PAD   100096        // multiple of 64-row tiles
#define N_EDGES 1600000
#define D 128
#define SCAN_B 1024
#define N_SCAN_BLOCKS ((N_NODES + SCAN_B - 1) / SCAN_B)   // 98

using namespace nvcuda;

// Scratch (allocation-free rule: __device__ globals)
__device__ __half g_hs[(size_t)N_PAD * D];   // hs = (x @ W) * dinv[row], fp16
__device__ float  g_x[(size_t)N_PAD * D];    // layer activations (pad rows 0)
__device__ float  g_dinv[N_NODES];
__device__ int    g_is64;
__device__ int    g_erow[N_EDGES];
__device__ int    g_ecol[N_EDGES];
__device__ int    g_cnt[N_NODES];
__device__ int    g_rowptr[N_NODES + 1];
__device__ int    g_cursor[N_NODES];
__device__ int    g_src[N_EDGES];
__device__ int    g_bsum[N_SCAN_BLOCKS];

// ===========================================================================
// Setup: decode, degree histogram, scan, CSR fill
// ===========================================================================
__global__ void k_detect(const unsigned int* __restrict__ buf) {
    __shared__ unsigned int acc;
    if (threadIdx.x == 0) acc = 0u;
    __syncthreads();
    unsigned int local = 0u;
    for (int i = threadIdx.x; i < 4096; i += blockDim.x)
        local |= buf[2 * i + 1];
    atomicOr(&acc, local);
    __syncthreads();
    if (threadIdx.x == 0) g_is64 = (acc == 0u) ? 1 : 0;
}

__global__ void k_zero() {
    int i = blockIdx.x * blockDim.x + threadIdx.x;
    if (i < N_NODES) { g_cnt[i] = 0; g_cursor[i] = 0; }
}

__global__ void k_convert_hist(const void* __restrict__ buf) {
    int e = blockIdx.x * blockDim.x + threadIdx.x;
    if (e >= N_EDGES) return;
    int r, c;
    if (g_is64) {
        const long long* p = (const long long*)buf;
        r = (int)p[e];
        c = (int)p[e + N_EDGES];
    } else {
        const int* p = (const int*)buf;
        r = p[e];
        c = p[e + N_EDGES];
    }
    g_erow[e] = r;
    g_ecol[e] = c;
    atomicAdd(&g_cnt[c], 1);
}

__global__ void __launch_bounds__(SCAN_B)
k_scan1() {
    __shared__ int s[SCAN_B];
    int i = blockIdx.x * SCAN_B + threadIdx.x;
    int v = (i < N_NODES) ? g_cnt[i] : 0;
    if (i < N_NODES) g_dinv[i] = rsqrtf(1.0f + (float)v);
    s[threadIdx.x] = v;
    __syncthreads();
#pragma unroll
    for (int off = 1; off < SCAN_B; off <<= 1) {
        int t = (threadIdx.x >= off) ? s[threadIdx.x - off] : 0;
        __syncthreads();
        s[threadIdx.x] += t;
        __syncthreads();
    }
    if (i < N_NODES) g_rowptr[i] = s[threadIdx.x] - v;
    if (threadIdx.x == SCAN_B - 1) g_bsum[blockIdx.x] = s[SCAN_B - 1];
}

__global__ void k_scan2() {
    __shared__ int s[128];
    int t = threadIdx.x;
    int v = (t < N_SCAN_BLOCKS) ? g_bsum[t] : 0;
    s[t] = v;
    __syncthreads();
#pragma unroll
    for (int off = 1; off < 128; off <<= 1) {
        int tv = (t >= off) ? s[t - off] : 0;
        __syncthreads();
        s[t] += tv;
        __syncthreads();
    }
    if (t < N_SCAN_BLOCKS) g_bsum[t] = s[t] - v;   // exclusive
    if (t == 0) g_rowptr[N_NODES] = N_EDGES;
}

__global__ void k_scan3() {
    int i = blockIdx.x * blockDim.x + threadIdx.x;
    if (i < N_NODES) g_rowptr[i] += g_bsum[i / SCAN_B];
}

__global__ void k_fill() {
    int e = blockIdx.x * blockDim.x + threadIdx.x;
    if (e >= N_EDGES) return;
    int c = g_ecol[e];
    int pos = atomicAdd(&g_cursor[c], 1);
    g_src[g_rowptr[c] + pos] = g_erow[e];
}

// ===========================================================================
// GEMM (TF32 wmma) + epilogue hs = (A@W)*dinv as fp16.
// 64-row tile, 256 threads = 8 warps (2M x 4N), warp tile 32x32.
// ===========================================================================
#define LDMF 136
#define GEMM_SMEM ((64 + 128) * LDMF * 4)   // 104448 B -> occupancy 2

__device__ __forceinline__ uint32_t pack_h2(float a, float b) {
    __half2 h = __floats2half2_rn(a, b);
    return *(uint32_t*)&h;
}

template<bool FROM_GX>
__global__ void __launch_bounds__(256, 2)
k_gemm_tf32(const float* __restrict__ Ain, const float* __restrict__ W) {
    extern __shared__ float sm[];
    float* As = sm;                 // [64][LDMF]  (reused for D staging)
    float* Bs = sm + 64 * LDMF;     // [128][LDMF]

    const int tid = threadIdx.x;
    const int wid = tid >> 5;
    const int wm = wid >> 2;
    const int wn = wid & 3;
    const int row0 = blockIdx.x * 64;
    const float* A = FROM_GX ? g_x : Ain;

    const float4* A4 = (const float4*)A;
    const float4* W4 = (const float4*)W;

    for (int idx = tid; idx < 4096; idx += 256) {
        int r = idx >> 5, c4 = idx & 31;
        float4 v = W4[r * 32 + c4];
        float* dst = Bs + r * LDMF + c4 * 4;
        dst[0] = wmma::__float_to_tf32(v.x);
        dst[1] = wmma::__float_to_tf32(v.y);
        dst[2] = wmma::__float_to_tf32(v.z);
        dst[3] = wmma::__float_to_tf32(v.w);
    }
    for (int idx = tid; idx < 2048; idx += 256) {
        int r = idx >> 5, c4 = idx & 31;
        int row = row0 + r;
        float4 v = (row < N_NODES) ? A4[(size_t)row * 32 + c4]
                                   : make_float4(0.f, 0.f, 0.f, 0.f);
        float* dst = As + r * LDMF + c4 * 4;
        dst[0] = wmma::__float_to_tf32(v.x);
        dst[1] = wmma::__float_to_tf32(v.y);
        dst[2] = wmma::__float_to_tf32(v.z);
        dst[3] = wmma::__float_to_tf32(v.w);
    }
    __syncthreads();

    wmma::fragment<wmma::accumulator, 16, 16, 8, float> c[2][2];
#pragma unroll
    for (int i = 0; i < 2; i++)
#pragma unroll
        for (int j = 0; j < 2; j++) wmma::fill_fragment(c[i][j], 0.0f);

#pragma unroll
    for (int k = 0; k < 16; k++) {
        wmma::fragment<wmma::matrix_a, 16, 16, 8, wmma::precision::tf32,
                       wmma::row_major> a[2];
        wmma::fragment<wmma::matrix_b, 16, 16, 8, wmma::precision::tf32,
                       wmma::row_major> b[2];
#pragma unroll
        for (int i = 0; i < 2; i++)
            wmma::load_matrix_sync(a[i], As + (wm * 32 + i * 16) * LDMF + k * 8,
                                   LDMF);
#pragma unroll
        for (int j = 0; j < 2; j++)
            wmma::load_matrix_sync(b[j], Bs + (k * 8) * LDMF + wn * 32 + j * 16,
                                   LDMF);
#pragma unroll
        for (int i = 0; i < 2; i++)
#pragma unroll
            for (int j = 0; j < 2; j++)
                wmma::mma_sync(c[i][j], a[i], b[j], c[i][j]);
    }

    // Stage D into As (all warps done reading As after this barrier)
    __syncthreads();
#pragma unroll
    for (int i = 0; i < 2; i++)
#pragma unroll
        for (int j = 0; j < 2; j++)
            wmma::store_matrix_sync(As + (wm * 32 + i * 16) * LDMF +
                                        wn * 32 + j * 16,
                                    c[i][j], LDMF, wmma::mem_row_major);
    __syncthreads();

    // Convert to fp16 hs = h * dinv[row]; each thread: 1 row-quarter (32 vals)
    {
        int r = tid >> 2;             // 0..63
        int q = tid & 3;              // 0..3 -> cols q*32..q*32+31
        int row = row0 + r;
        float s = (row < N_NODES) ? g_dinv[row] : 0.0f;
        const float* src = As + r * LDMF + q * 32;
        uint4* dst = (uint4*)(g_hs + (size_t)row * D) + q * 4;
#pragma unroll
        for (int i = 0; i < 4; i++) {
            uint4 o;
            o.x = pack_h2(src[i * 8 + 0] * s, src[i * 8 + 1] * s);
            o.y = pack_h2(src[i * 8 + 2] * s, src[i * 8 + 3] * s);
            o.z = pack_h2(src[i * 8 + 4] * s, src[i * 8 + 5] * s);
            o.w = pack_h2(src[i * 8 + 6] * s, src[i * 8 + 7] * s);
            dst[i] = o;
        }
    }
}

// ===========================================================================
// Aggregation: one warp per target node, fp16 gather, fp32 accumulate.
// x[c] = relu( bias + dinv[c] * ( hs[c] + sum_{r in CSR(c)} hs[r] ) )
// ===========================================================================
__global__ void __launch_bounds__(256)
k_aggregate(const float* __restrict__ bias, float* __restrict__ out,
            int use_out) {
    int node = (blockIdx.x * blockDim.x + threadIdx.x) >> 5;
    int lane = threadIdx.x & 31;
    if (node >= N_NODES) return;

    float* dst = use_out ? out : g_x;
    float dinv_c = g_dinv[node];
    const uint2* HS = (const uint2*)g_hs;   // 32 uint2 per row

    // self term (hs already includes dinv[node])
    uint2 v = HS[(size_t)node * 32 + lane];
    float2 f0 = __half22float2(*(__half2*)&v.x);
    float2 f1 = __half22float2(*(__half2*)&v.y);
    float4 acc0 = make_float4(f0.x, f0.y, f1.x, f1.y);
    float4 acc1 = make_float4(0.f, 0.f, 0.f, 0.f);

    int beg = g_rowptr[node];
    int end = g_rowptr[node + 1];
    for (int base = beg; base < end; base += 32) {
        int j = base + lane;
        int r = (j < end) ? g_src[j] : 0;
        int cnt = min(32, end - base);
        int k = 0;
        for (; k + 1 < cnt; k += 2) {
            int r0 = __shfl_sync(0xffffffffu, r, k);
            int r1 = __shfl_sync(0xffffffffu, r, k + 1);
            uint2 v0 = HS[(size_t)r0 * 32 + lane];
            uint2 v1 = HS[(size_t)r1 * 32 + lane];
            float2 a0 = __half22float2(*(__half2*)&v0.x);
            float2 a1 = __half22float2(*(__half2*)&v0.y);
            float2 b0 = __half22float2(*(__half2*)&v1.x);
            float2 b1 = __half22float2(*(__half2*)&v1.y);
            acc0.x += a0.x; acc0.y += a0.y; acc0.z += a1.x; acc0.w += a1.y;
            acc1.x += b0.x; acc1.y += b0.y; acc1.z += b1.x; acc1.w += b1.y;
        }
        if (k < cnt) {
            int r0 = __shfl_sync(0xffffffffu, r, k);
            uint2 v0 = HS[(size_t)r0 * 32 + lane];
            float2 a0 = __half22float2(*(__half2*)&v0.x);
            float2 a1 = __half22float2(*(__half2*)&v0.y);
            acc0.x += a0.x; acc0.y += a0.y; acc0.z += a1.x; acc0.w += a1.y;
        }
    }

    float4 bb = ((const float4*)bias)[lane];
    float4 x;
    x.x = fmaf(dinv_c, acc0.x + acc1.x, bb.x);
    x.y = fmaf(dinv_c, acc0.y + acc1.y, bb.y);
    x.z = fmaf(dinv_c, acc0.z + acc1.z, bb.z);
    x.w = fmaf(dinv_c, acc0.w + acc1.w, bb.w);
    x.x = fmaxf(x.x, 0.f); x.y = fmaxf(x.y, 0.f);
    x.z = fmaxf(x.z, 0.f); x.w = fmaxf(x.w, 0.f);
    ((float4*)(dst + (size_t)node * D))[lane] = x;
}

// ===========================================================================
// Launch
// ===========================================================================
extern "C" void kernel_launch(void* const* d_in, const int* in_sizes, int n_in,
                              void* d_out, int out_size) {
    const void* edge = d_in[0];
    const float* emb = (const float*)d_in[1];
    const float* Ws  = (const float*)d_in[2];
    const float* bs  = (const float*)d_in[3];
    float* out = (float*)d_out;

    static bool attr_done = false;
    if (!attr_done) {
        cudaFuncSetAttribute(k_gemm_tf32<false>,
                             cudaFuncAttributeMaxDynamicSharedMemorySize, GEMM_SMEM);
        cudaFuncSetAttribute(k_gemm_tf32<true>,
                             cudaFuncAttributeMaxDynamicSharedMemorySize, GEMM_SMEM);
        attr_done = true;
    }

    const int nb_nodes = (N_NODES + 255) / 256;
    const int nb_edges = (N_EDGES + 255) / 256;

    k_detect<<<1, 256>>>((const unsigned int*)edge);
    k_zero<<<nb_nodes, 256>>>();
    k_convert_hist<<<nb_edges, 256>>>(edge);
    k_scan1<<<N_SCAN_BLOCKS, SCAN_B>>>();
    k_scan2<<<1, 128>>>();
    k_scan3<<<nb_nodes, 256>>>();
    k_fill<<<nb_edges, 256>>>();

    const int gemm_blocks = N_PAD / 64;                  // 1564
    const int agg_blocks = (N_NODES * 32 + 255) / 256;   // 12500

    // Layer 0
    k_gemm_tf32<false><<<gemm_blocks, 256, GEMM_SMEM>>>(emb, Ws + 0 * D * D);
    k_aggregate<<<agg_blocks, 256>>>(bs + 0 * D, out, 0);
    // Layer 1
    k_gemm_tf32<true><<<gemm_blocks, 256, GEMM_SMEM>>>(nullptr, Ws + 1 * D * D);
    k_aggregate<<<agg_blocks, 256>>>(bs + 1 * D, out, 0);
    // Layer 2 -> d_out (ReLU in aggregate)
    k_gemm_tf32<true><<<gemm_blocks, 256, GEMM_SMEM>>>(nullptr, Ws + 2 * D * D);
    k_aggregate<<<agg_blocks, 256>>>(bs + 2 * D, out, 1);
}

// round 9
// speedup vs baseline: 1.2120x; 1.0290x over previous
#include <cuda_runtime.h>
#include <cuda_fp16.h>
#include <mma.h>
#include <cstdint>

#define N_NODES 100000
#define N_PAD   100096        // multiple of 64-row tiles
#define N_EDGES 1600000
#define D 128
#define SCAN_B 1024
#define N_SCAN_BLOCKS ((N_NODES + SCAN_B - 1) / SCAN_B)   // 98

using namespace nvcuda;

// Scratch (allocation-free rule: __device__ globals)
__device__ __half g_hs[(size_t)N_PAD * D];   // hs = (x @ W) * dinv[row], fp16
__device__ float  g_x[(size_t)N_PAD * D];    // tf32-rounded activations
__device__ float  g_w[3 * D * D];            // tf32-rounded weights
__device__ float  g_dinv[N_NODES];
__device__ int    g_is64;
__device__ int    g_erow[N_EDGES];
__device__ int    g_ecol[N_EDGES];
__device__ int    g_cnt[N_NODES];
__device__ int    g_rowptr[N_NODES + 1];
__device__ int    g_cursor[N_NODES];
__device__ int    g_src[N_EDGES];
__device__ int    g_bsum[N_SCAN_BLOCKS];

// ===========================================================================
// Setup
// ===========================================================================
__global__ void k_detect(const unsigned int* __restrict__ buf) {
    __shared__ unsigned int acc;
    if (threadIdx.x == 0) acc = 0u;
    __syncthreads();
    unsigned int local = 0u;
    for (int i = threadIdx.x; i < 4096; i += blockDim.x)
        local |= buf[2 * i + 1];
    atomicOr(&acc, local);
    __syncthreads();
    if (threadIdx.x == 0) g_is64 = (acc == 0u) ? 1 : 0;
}

__global__ void k_zero() {
    int i = blockIdx.x * blockDim.x + threadIdx.x;
    if (i < N_NODES) { g_cnt[i] = 0; g_cursor[i] = 0; }
}

__global__ void k_convert_hist(const void* __restrict__ buf) {
    int e = blockIdx.x * blockDim.x + threadIdx.x;
    if (e >= N_EDGES) return;
    int r, c;
    if (g_is64) {
        const long long* p = (const long long*)buf;
        r = (int)p[e];
        c = (int)p[e + N_EDGES];
    } else {
        const int* p = (const int*)buf;
        r = p[e];
        c = p[e + N_EDGES];
    }
    g_erow[e] = r;
    g_ecol[e] = c;
    atomicAdd(&g_cnt[c], 1);
}

__global__ void __launch_bounds__(SCAN_B)
k_scan1() {
    __shared__ int s[SCAN_B];
    int i = blockIdx.x * SCAN_B + threadIdx.x;
    int v = (i < N_NODES) ? g_cnt[i] : 0;
    if (i < N_NODES) g_dinv[i] = rsqrtf(1.0f + (float)v);
    s[threadIdx.x] = v;
    __syncthreads();
#pragma unroll
    for (int off = 1; off < SCAN_B; off <<= 1) {
        int t = (threadIdx.x >= off) ? s[threadIdx.x - off] : 0;
        __syncthreads();
        s[threadIdx.x] += t;
        __syncthreads();
    }
    if (i < N_NODES) g_rowptr[i] = s[threadIdx.x] - v;
    if (threadIdx.x == SCAN_B - 1) g_bsum[blockIdx.x] = s[SCAN_B - 1];
}

__global__ void k_scan2() {
    __shared__ int s[128];
    int t = threadIdx.x;
    int v = (t < N_SCAN_BLOCKS) ? g_bsum[t] : 0;
    s[t] = v;
    __syncthreads();
#pragma unroll
    for (int off = 1; off < 128; off <<= 1) {
        int tv = (t >= off) ? s[t - off] : 0;
        __syncthreads();
        s[t] += tv;
        __syncthreads();
    }
    if (t < N_SCAN_BLOCKS) g_bsum[t] = s[t] - v;   // exclusive
    if (t == 0) g_rowptr[N_NODES] = N_EDGES;
}

__global__ void k_scan3() {
    int i = blockIdx.x * blockDim.x + threadIdx.x;
    if (i < N_NODES) g_rowptr[i] += g_bsum[i / SCAN_B];
}

__global__ void k_fill() {
    int e = blockIdx.x * blockDim.x + threadIdx.x;
    if (e >= N_EDGES) return;
    int c = g_ecol[e];
    int pos = atomicAdd(&g_cursor[c], 1);
    g_src[g_rowptr[c] + pos] = g_erow[e];
}

// Round W (3 layers) to tf32-RN into g_w
__global__ void k_round_w(const float* __restrict__ Ws) {
    int i = blockIdx.x * blockDim.x + threadIdx.x;
    if (i < 3 * D * D) g_w[i] = wmma::__float_to_tf32(Ws[i]);
}

// Round emb to tf32-RN into g_x (layer-0 input); pad rows stay 0
__global__ void k_round_emb(const float* __restrict__ emb) {
    int i = blockIdx.x * blockDim.x + threadIdx.x;   // float4 index
    if (i < N_NODES * 32) {
        float4 v = ((const float4*)emb)[i];
        v.x = wmma::__float_to_tf32(v.x);
        v.y = wmma::__float_to_tf32(v.y);
        v.z = wmma::__float_to_tf32(v.z);
        v.w = wmma::__float_to_tf32(v.w);
        ((float4*)g_x)[i] = v;
    }
}

// ===========================================================================
// Smem-free TF32 wmma GEMM: warp = 64x32 output tile, frags loaded straight
// from GLOBAL (L1/L2-cached; inputs pre-rounded so HW truncation == RN).
// Epilogue: hs = (A@W)*dinv[row] -> fp16, staged via 18KB static smem.
// ===========================================================================
__global__ void __launch_bounds__(256, 2)
k_gemm(const float* __restrict__ Wr) {
    __shared__ float stage[8][16 * 36];   // per-warp 16x32 strip, pad 36

    const int wid = threadIdx.x >> 5;
    const int lane = threadIdx.x & 31;
    const int gw = blockIdx.x * 8 + wid;      // 6256 warps total
    const int mt = gw >> 2;                   // 64-row tile
    const int nt = gw & 3;                    // 32-col strip
    const int row0 = mt * 64;
    const int col0 = nt * 32;

    wmma::fragment<wmma::accumulator, 16, 16, 8, float> acc[4][2];
#pragma unroll
    for (int i = 0; i < 4; i++)
#pragma unroll
        for (int j = 0; j < 2; j++) wmma::fill_fragment(acc[i][j], 0.0f);

#pragma unroll 4
    for (int k = 0; k < 16; k++) {
        wmma::fragment<wmma::matrix_b, 16, 16, 8, wmma::precision::tf32,
                       wmma::row_major> b[2];
#pragma unroll
        for (int j = 0; j < 2; j++)
            wmma::load_matrix_sync(b[j], Wr + (k * 8) * D + col0 + j * 16, D);
#pragma unroll
        for (int i = 0; i < 4; i++) {
            wmma::fragment<wmma::matrix_a, 16, 16, 8, wmma::precision::tf32,
                           wmma::row_major> a;
            wmma::load_matrix_sync(a, g_x + (size_t)(row0 + i * 16) * D + k * 8,
                                   D);
            wmma::mma_sync(acc[i][0], a, b[0], acc[i][0]);
            wmma::mma_sync(acc[i][1], a, b[1], acc[i][1]);
        }
    }

    // Epilogue: per 16-row strip, stage fp32 -> scale by dinv -> fp16 store
#pragma unroll
    for (int i = 0; i < 4; i++) {
        wmma::store_matrix_sync(&stage[wid][0], acc[i][0], 36,
                                wmma::mem_row_major);
        wmma::store_matrix_sync(&stage[wid][16], acc[i][1], 36,
                                wmma::mem_row_major);
        __syncwarp();
        int r = lane >> 1;                 // 0..15
        int ch = (lane & 1) * 16;          // col half within strip
        int row = row0 + i * 16 + r;
        float s = (row < N_NODES) ? g_dinv[row] : 0.0f;
        const float* src = &stage[wid][r * 36 + ch];
        // 16 floats -> 8 half2 -> 2 uint4 stores
        uint4 o0, o1;
        {
            __half2 h;
            h = __floats2half2_rn(src[0] * s,  src[1] * s);  o0.x = *(uint32_t*)&h;
            h = __floats2half2_rn(src[2] * s,  src[3] * s);  o0.y = *(uint32_t*)&h;
            h = __floats2half2_rn(src[4] * s,  src[5] * s);  o0.z = *(uint32_t*)&h;
            h = __floats2half2_rn(src[6] * s,  src[7] * s);  o0.w = *(uint32_t*)&h;
            h = __floats2half2_rn(src[8] * s,  src[9] * s);  o1.x = *(uint32_t*)&h;
            h = __floats2half2_rn(src[10] * s, src[11] * s); o1.y = *(uint32_t*)&h;
            h = __floats2half2_rn(src[12] * s, src[13] * s); o1.z = *(uint32_t*)&h;
            h = __floats2half2_rn(src[14] * s, src[15] * s); o1.w = *(uint32_t*)&h;
        }
        uint4* dst = (uint4*)(g_hs + (size_t)row * D + col0 + ch);
        dst[0] = o0;
        dst[1] = o1;
        __syncwarp();
    }
}

// ===========================================================================
// Aggregation: one warp per target node, fp16 gather, fp32 accumulate.
// Internal layers write tf32-RN-rounded x (== what the GEMM would round).
// ===========================================================================
__global__ void __launch_bounds__(256)
k_aggregate(const float* __restrict__ bias, float* __restrict__ out,
            int use_out) {
    int node = (blockIdx.x * blockDim.x + threadIdx.x) >> 5;
    int lane = threadIdx.x & 31;
    if (node >= N_NODES) return;

    float dinv_c = g_dinv[node];
    const uint2* HS = (const uint2*)g_hs;   // 32 uint2 per row

    uint2 v = HS[(size_t)node * 32 + lane];
    float2 f0 = __half22float2(*(__half2*)&v.x);
    float2 f1 = __half22float2(*(__half2*)&v.y);
    float4 acc0 = make_float4(f0.x, f0.y, f1.x, f1.y);
    float4 acc1 = make_float4(0.f, 0.f, 0.f, 0.f);

    int beg = g_rowptr[node];
    int end = g_rowptr[node + 1];
    for (int base = beg; base < end; base += 32) {
        int j = base + lane;
        int r = (j < end) ? g_src[j] : 0;
        int cnt = min(32, end - base);
        int k = 0;
        for (; k + 1 < cnt; k += 2) {
            int r0 = __shfl_sync(0xffffffffu, r, k);
            int r1 = __shfl_sync(0xffffffffu, r, k + 1);
            uint2 v0 = HS[(size_t)r0 * 32 + lane];
            uint2 v1 = HS[(size_t)r1 * 32 + lane];
            float2 a0 = __half22float2(*(__half2*)&v0.x);
            float2 a1 = __half22float2(*(__half2*)&v0.y);
            float2 b0 = __half22float2(*(__half2*)&v1.x);
            float2 b1 = __half22float2(*(__half2*)&v1.y);
            acc0.x += a0.x; acc0.y += a0.y; acc0.z += a1.x; acc0.w += a1.y;
            acc1.x += b0.x; acc1.y += b0.y; acc1.z += b1.x; acc1.w += b1.y;
        }
        if (k < cnt) {
            int r0 = __shfl_sync(0xffffffffu, r, k);
            uint2 v0 = HS[(size_t)r0 * 32 + lane];
            float2 a0 = __half22float2(*(__half2*)&v0.x);
            float2 a1 = __half22float2(*(__half2*)&v0.y);
            acc0.x += a0.x; acc0.y += a0.y; acc0.z += a1.x; acc0.w += a1.y;
        }
    }

    float4 bb = ((const float4*)bias)[lane];
    float4 x;
    x.x = fmaxf(fmaf(dinv_c, acc0.x + acc1.x, bb.x), 0.f);
    x.y = fmaxf(fmaf(dinv_c, acc0.y + acc1.y, bb.y), 0.f);
    x.z = fmaxf(fmaf(dinv_c, acc0.z + acc1.z, bb.z), 0.f);
    x.w = fmaxf(fmaf(dinv_c, acc0.w + acc1.w, bb.w), 0.f);

    if (use_out) {
        ((float4*)(out + (size_t)node * D))[lane] = x;
    } else {
        x.x = wmma::__float_to_tf32(x.x);
        x.y = wmma::__float_to_tf32(x.y);
        x.z = wmma::__float_to_tf32(x.z);
        x.w = wmma::__float_to_tf32(x.w);
        ((float4*)(g_x + (size_t)node * D))[lane] = x;
    }
}

// ===========================================================================
// Launch
// ===========================================================================
extern "C" void kernel_launch(void* const* d_in, const int* in_sizes, int n_in,
                              void* d_out, int out_size) {
    const void* edge = d_in[0];
    const float* emb = (const float*)d_in[1];
    const float* Ws  = (const float*)d_in[2];
    const float* bs  = (const float*)d_in[3];
    float* out = (float*)d_out;

    float* g_w_p;
    cudaGetSymbolAddress((void**)&g_w_p, g_w);

    const int nb_nodes = (N_NODES + 255) / 256;
    const int nb_edges = (N_EDGES + 255) / 256;

    k_detect<<<1, 256>>>((const unsigned int*)edge);
    k_zero<<<nb_nodes, 256>>>();
    k_convert_hist<<<nb_edges, 256>>>(edge);
    k_scan1<<<N_SCAN_BLOCKS, SCAN_B>>>();
    k_scan2<<<1, 128>>>();
    k_scan3<<<nb_nodes, 256>>>();
    k_fill<<<nb_edges, 256>>>();
    k_round_w<<<(3 * D * D + 255) / 256, 256>>>(Ws);
    k_round_emb<<<(N_NODES * 32 + 255) / 256, 256>>>(emb);

    const int gemm_blocks = (N_PAD / 64) * 4 / 8;        // 782
    const int agg_blocks = (N_NODES * 32 + 255) / 256;   // 12500

    // Layer 0
    k_gemm<<<gemm_blocks, 256>>>(g_w_p + 0 * D * D);
    k_aggregate<<<agg_blocks, 256>>>(bs + 0 * D, out, 0);
    // Layer 1
    k_gemm<<<gemm_blocks, 256>>>(g_w_p + 1 * D * D);
    k_aggregate<<<agg_blocks, 256>>>(bs + 1 * D, out, 0);
    // Layer 2 -> d_out (ReLU in aggregate)
    k_gemm<<<gemm_blocks, 256>>>(g_w_p + 2 * D * D);
    k_aggregate<<<agg_blocks, 256>>>(bs + 2 * D, out, 1);
}

// round 11
// speedup vs baseline: 1.8282x; 1.5084x over previous
#include <cuda_runtime.h>
#include <cuda_fp16.h>
#include <mma.h>
#include <cstdint>

#define N_NODES 100000
#define N_PAD   100096        // multiple of 128-row tiles
#define N_EDGES 1600000
#define D 128
#define SCAN_B 1024
#define N_SCAN_BLOCKS ((N_NODES + SCAN_B - 1) / SCAN_B)   // 98

using namespace nvcuda;

// Scratch (allocation-free rule: __device__ globals; zero-initialized)
__device__ __half g_hs[(size_t)N_PAD * D];   // hs = (x @ W) * dinv[row], fp16
__device__ __half g_xh[(size_t)N_PAD * D];   // activations, fp16 (pad rows 0)
__device__ __half g_w16[3 * D * D];          // weights, fp16
__device__ float  g_dinv[N_NODES];
__device__ int    g_is64;
__device__ int    g_erow[N_EDGES];
__device__ int    g_ecol[N_EDGES];
__device__ int    g_cnt[N_NODES];
__device__ int    g_rowptr[N_NODES + 1];
__device__ int    g_cursor[N_NODES];
__device__ int    g_src[N_EDGES];
__device__ int    g_bsum[N_SCAN_BLOCKS];

// ===========================================================================
// Setup
// ===========================================================================
__global__ void k_detect(const unsigned int* __restrict__ buf) {
    __shared__ unsigned int acc;
    if (threadIdx.x == 0) acc = 0u;
    __syncthreads();
    unsigned int local = 0u;
    for (int i = threadIdx.x; i < 4096; i += blockDim.x)
        local |= buf[2 * i + 1];
    atomicOr(&acc, local);
    __syncthreads();
    if (threadIdx.x == 0) g_is64 = (acc == 0u) ? 1 : 0;
}

__global__ void k_zero() {
    int i = blockIdx.x * blockDim.x + threadIdx.x;
    if (i < N_NODES) { g_cnt[i] = 0; g_cursor[i] = 0; }
}

__global__ void k_convert_hist(const void* __restrict__ buf) {
    int e = blockIdx.x * blockDim.x + threadIdx.x;
    if (e >= N_EDGES) return;
    int r, c;
    if (g_is64) {
        const long long* p = (const long long*)buf;
        r = (int)p[e];
        c = (int)p[e + N_EDGES];
    } else {
        const int* p = (const int*)buf;
        r = p[e];
        c = p[e + N_EDGES];
    }
    g_erow[e] = r;
    g_ecol[e] = c;
    atomicAdd(&g_cnt[c], 1);
}

__global__ void __launch_bounds__(SCAN_B)
k_scan1() {
    __shared__ int s[SCAN_B];
    int i = blockIdx.x * SCAN_B + threadIdx.x;
    int v = (i < N_NODES) ? g_cnt[i] : 0;
    if (i < N_NODES) g_dinv[i] = rsqrtf(1.0f + (float)v);
    s[threadIdx.x] = v;
    __syncthreads();
#pragma unroll
    for (int off = 1; off < SCAN_B; off <<= 1) {
        int t = (threadIdx.x >= off) ? s[threadIdx.x - off] : 0;
        __syncthreads();
        s[threadIdx.x] += t;
        __syncthreads();
    }
    if (i < N_NODES) g_rowptr[i] = s[threadIdx.x] - v;
    if (threadIdx.x == SCAN_B - 1) g_bsum[blockIdx.x] = s[SCAN_B - 1];
}

__global__ void k_scan2() {
    __shared__ int s[128];
    int t = threadIdx.x;
    int v = (t < N_SCAN_BLOCKS) ? g_bsum[t] : 0;
    s[t] = v;
    __syncthreads();
#pragma unroll
    for (int off = 1; off < 128; off <<= 1) {
        int tv = (t >= off) ? s[t - off] : 0;
        __syncthreads();
        s[t] += tv;
        __syncthreads();
    }
    if (t < N_SCAN_BLOCKS) g_bsum[t] = s[t] - v;   // exclusive
    if (t == 0) g_rowptr[N_NODES] = N_EDGES;
}

__global__ void k_scan3() {
    int i = blockIdx.x * blockDim.x + threadIdx.x;
    if (i < N_NODES) g_rowptr[i] += g_bsum[i / SCAN_B];
}

__global__ void k_fill() {
    int e = blockIdx.x * blockDim.x + threadIdx.x;
    if (e >= N_EDGES) return;
    int c = g_ecol[e];
    int pos = atomicAdd(&g_cursor[c], 1);
    g_src[g_rowptr[c] + pos] = g_erow[e];
}

// Convert W (3 layers) and emb to fp16
__global__ void k_w2h(const float* __restrict__ Ws) {
    int i = blockIdx.x * blockDim.x + threadIdx.x;
    if (i < 3 * D * D) g_w16[i] = __float2half_rn(Ws[i]);
}

__global__ void k_emb2h(const float* __restrict__ emb) {
    int i = blockIdx.x * blockDim.x + threadIdx.x;   // 8-half chunk index
    if (i >= N_NODES * 16) return;
    const float4* src = (const float4*)emb + i * 2;
    float4 v0 = src[0], v1 = src[1];
    uint4 o;
    __half2 h;
    h = __floats2half2_rn(v0.x, v0.y); o.x = *(uint32_t*)&h;
    h = __floats2half2_rn(v0.z, v0.w); o.y = *(uint32_t*)&h;
    h = __floats2half2_rn(v1.x, v1.y); o.z = *(uint32_t*)&h;
    h = __floats2half2_rn(v1.z, v1.w); o.w = *(uint32_t*)&h;
    ((uint4*)g_xh)[i] = o;
}

// ===========================================================================
// fp16 wmma GEMM: block = 128x128 tile, 8 warps (4M x 2N), warp 32x64.
// LDM = 136 halfs (272B stride): conflict-free LDSM. Accumulate fp32.
// Epilogue: hs = (A@W) * dinv[row] as fp16 (each lane: one 32-col half-row).
// ===========================================================================
#define LDH 136
#define GEMM_SMEM (2 * 128 * LDH * 2)      // A + W tiles, 69632 B

__global__ void __launch_bounds__(256, 2)
k_gemm(const __half* __restrict__ Wl) {
    extern __shared__ __half smh[];
    __half* As = smh;                 // [128][LDH]
    __half* Wsm = smh + 128 * LDH;    // [128][LDH]
    __shared__ float stage[8][16 * 68];   // per-warp epilogue strip

    const int tid = threadIdx.x;
    const int wid = tid >> 5;
    const int lane = tid & 31;
    const int wm = wid >> 1;          // 0..3 -> 32-row strip
    const int wn = wid & 1;           // 0..1 -> 64-col strip
    const int row0 = blockIdx.x * 128;

    // Fill W tile: 128 rows x 16 uint4 = 2048, 8 per thread
    for (int idx = tid; idx < 2048; idx += 256) {
        int r = idx >> 4, c8 = idx & 15;
        uint4 v = ((const uint4*)(Wl + r * D))[c8];
        *(uint4*)(Wsm + r * LDH + c8 * 8) = v;
    }
    // Fill A tile: 128 rows x 16 uint4 = 2048 (guard rows >= N_NODES)
    for (int idx = tid; idx < 2048; idx += 256) {
        int r = idx >> 4, c8 = idx & 15;
        int row = row0 + r;
        uint4 v = make_uint4(0u, 0u, 0u, 0u);
        if (row < N_NODES) v = ((const uint4*)(g_xh + (size_t)row * D))[c8];
        *(uint4*)(As + r * LDH + c8 * 8) = v;
    }
    __syncthreads();

    wmma::fragment<wmma::accumulator, 16, 16, 16, float> acc[2][4];
#pragma unroll
    for (int i = 0; i < 2; i++)
#pragma unroll
        for (int j = 0; j < 4; j++) wmma::fill_fragment(acc[i][j], 0.0f);

#pragma unroll
    for (int k = 0; k < 8; k++) {
        wmma::fragment<wmma::matrix_a, 16, 16, 16, __half, wmma::row_major> a[2];
        wmma::fragment<wmma::matrix_b, 16, 16, 16, __half, wmma::row_major> b[4];
#pragma unroll
        for (int i = 0; i < 2; i++)
            wmma::load_matrix_sync(a[i], As + (wm * 32 + i * 16) * LDH + k * 16,
                                   LDH);
#pragma unroll
        for (int j = 0; j < 4; j++)
            wmma::load_matrix_sync(b[j], Wsm + (k * 16) * LDH + wn * 64 + j * 16,
                                   LDH);
#pragma unroll
        for (int i = 0; i < 2; i++)
#pragma unroll
            for (int j = 0; j < 4; j++)
                wmma::mma_sync(acc[i][j], a[i], b[j], acc[i][j]);
    }

    // Epilogue: per 16-row x 64-col strip. Lane -> (row = lane>>1,
    // 32-col half = (lane&1)*32); converts ALL 32 floats of its half.
#pragma unroll
    for (int i = 0; i < 2; i++) {
#pragma unroll
        for (int j = 0; j < 4; j++)
            wmma::store_matrix_sync(&stage[wid][j * 16], acc[i][j], 68,
                                    wmma::mem_row_major);
        __syncwarp();
        int r = lane >> 1;                 // 0..15
        int ch = (lane & 1) * 32;          // 32-col half
        int row = row0 + wm * 32 + i * 16 + r;
        float s = (row < N_NODES) ? g_dinv[row] : 0.0f;
        const float* src = &stage[wid][r * 68 + ch];
        if (row < N_NODES) {
            uint4* dst = (uint4*)(g_hs + (size_t)row * D + wn * 64 + ch);
#pragma unroll
            for (int q = 0; q < 4; q++) {   // 4 x uint4 = 32 halves
                uint4 o;
                __half2 h;
                h = __floats2half2_rn(src[q * 8 + 0] * s, src[q * 8 + 1] * s);
                o.x = *(uint32_t*)&h;
                h = __floats2half2_rn(src[q * 8 + 2] * s, src[q * 8 + 3] * s);
                o.y = *(uint32_t*)&h;
                h = __floats2half2_rn(src[q * 8 + 4] * s, src[q * 8 + 5] * s);
                o.z = *(uint32_t*)&h;
                h = __floats2half2_rn(src[q * 8 + 6] * s, src[q * 8 + 7] * s);
                o.w = *(uint32_t*)&h;
                dst[q] = o;
            }
        }
        __syncwarp();
    }
}

// ===========================================================================
// Aggregation: one warp per target node, fp16 gather, fp32 accumulate.
// Internal layers write fp16 activations directly (GEMM input format).
// ===========================================================================
__global__ void __launch_bounds__(256)
k_aggregate(const float* __restrict__ bias, float* __restrict__ out,
            int use_out) {
    int node = (blockIdx.x * blockDim.x + threadIdx.x) >> 5;
    int lane = threadIdx.x & 31;
    if (node >= N_NODES) return;

    float dinv_c = g_dinv[node];
    const uint2* HS = (const uint2*)g_hs;   // 32 uint2 per row

    uint2 v = HS[(size_t)node * 32 + lane];
    float2 f0 = __half22float2(*(__half2*)&v.x);
    float2 f1 = __half22float2(*(__half2*)&v.y);
    float4 acc0 = make_float4(f0.x, f0.y, f1.x, f1.y);
    float4 acc1 = make_float4(0.f, 0.f, 0.f, 0.f);

    int beg = g_rowptr[node];
    int end = g_rowptr[node + 1];
    for (int base = beg; base < end; base += 32) {
        int j = base + lane;
        int r = (j < end) ? g_src[j] : 0;
        int cnt = min(32, end - base);
        int k = 0;
        for (; k + 1 < cnt; k += 2) {
            int r0 = __shfl_sync(0xffffffffu, r, k);
            int r1 = __shfl_sync(0xffffffffu, r, k + 1);
            uint2 v0 = HS[(size_t)r0 * 32 + lane];
            uint2 v1 = HS[(size_t)r1 * 32 + lane];
            float2 a0 = __half22float2(*(__half2*)&v0.x);
            float2 a1 = __half22float2(*(__half2*)&v0.y);
            float2 b0 = __half22float2(*(__half2*)&v1.x);
            float2 b1 = __half22float2(*(__half2*)&v1.y);
            acc0.x += a0.x; acc0.y += a0.y; acc0.z += a1.x; acc0.w += a1.y;
            acc1.x += b0.x; acc1.y += b0.y; acc1.z += b1.x; acc1.w += b1.y;
        }
        if (k < cnt) {
            int r0 = __shfl_sync(0xffffffffu, r, k);
            uint2 v0 = HS[(size_t)r0 * 32 + lane];
            float2 a0 = __half22float2(*(__half2*)&v0.x);
            float2 a1 = __half22float2(*(__half2*)&v0.y);
            acc0.x += a0.x; acc0.y += a0.y; acc0.z += a1.x; acc0.w += a1.y;
        }
    }

    float4 bb = ((const float4*)bias)[lane];
    float4 x;
    x.x = fmaxf(fmaf(dinv_c, acc0.x + acc1.x, bb.x), 0.f);
    x.y = fmaxf(fmaf(dinv_c, acc0.y + acc1.y, bb.y), 0.f);
    x.z = fmaxf(fmaf(dinv_c, acc0.z + acc1.z, bb.z), 0.f);
    x.w = fmaxf(fmaf(dinv_c, acc0.w + acc1.w, bb.w), 0.f);

    if (use_out) {
        ((float4*)(out + (size_t)node * D))[lane] = x;
    } else {
        uint2 o;
        __half2 h;
        h = __floats2half2_rn(x.x, x.y); o.x = *(uint32_t*)&h;
        h = __floats2half2_rn(x.z, x.w); o.y = *(uint32_t*)&h;
        ((uint2*)(g_xh + (size_t)node * D))[lane] = o;
    }
}

// ===========================================================================
// Launch
// ===========================================================================
extern "C" void kernel_launch(void* const* d_in, const int* in_sizes, int n_in,
                              void* d_out, int out_size) {
    const void* edge = d_in[0];
    const float* emb = (const float*)d_in[1];
    const float* Ws  = (const float*)d_in[2];
    const float* bs  = (const float*)d_in[3];
    float* out = (float*)d_out;

    __half* g_w16_p;
    cudaGetSymbolAddress((void**)&g_w16_p, g_w16);

    static bool attr_done = false;
    if (!attr_done) {
        cudaFuncSetAttribute(k_gemm,
                             cudaFuncAttributeMaxDynamicSharedMemorySize, GEMM_SMEM);
        attr_done = true;
    }

    const int nb_nodes = (N_NODES + 255) / 256;
    const int nb_edges = (N_EDGES + 255) / 256;

    k_detect<<<1, 256>>>((const unsigned int*)edge);
    k_zero<<<nb_nodes, 256>>>();
    k_convert_hist<<<nb_edges, 256>>>(edge);
    k_scan1<<<N_SCAN_BLOCKS, SCAN_B>>>();
    k_scan2<<<1, 128>>>();
    k_scan3<<<nb_nodes, 256>>>();
    k_fill<<<nb_edges, 256>>>();
    k_w2h<<<(3 * D * D + 255) / 256, 256>>>(Ws);
    k_emb2h<<<(N_NODES * 16 + 255) / 256, 256>>>(emb);

    const int gemm_blocks = N_PAD / 128;                 // 782
    const int agg_blocks = (N_NODES * 32 + 255) / 256;   // 12500

    // Layer 0
    k_gemm<<<gemm_blocks, 256, GEMM_SMEM>>>(g_w16_p + 0 * D * D);
    k_aggregate<<<agg_blocks, 256>>>(bs + 0 * D, out, 0);
    // Layer 1
    k_gemm<<<gemm_blocks, 256, GEMM_SMEM>>>(g_w16_p + 1 * D * D);
    k_aggregate<<<agg_blocks, 256>>>(bs + 1 * D, out, 0);
    // Layer 2 -> d_out (ReLU in aggregate)
    k_gemm<<<gemm_blocks, 256, GEMM_SMEM>>>(g_w16_p + 2 * D * D);
    k_aggregate<<<agg_blocks, 256>>>(bs + 2 * D, out, 1);
}

// round 12
// speedup vs baseline: 1.8996x; 1.0391x over previous
#include <cuda_runtime.h>
#include <cuda_fp16.h>
#include <mma.h>
#include <cstdint>

#define N_NODES 100000
#define N_PAD   100096        // multiple of 128-row tiles
#define N_EDGES 1600000
#define D 128
#define SCAN_B 1024
#define N_SCAN_BLOCKS ((N_NODES + SCAN_B - 1) / SCAN_B)   // 98

using namespace nvcuda;

// Scratch (allocation-free rule: __device__ globals; zero-initialized)
__device__ __half g_hs[(size_t)N_PAD * D];   // hs = (x @ W) * dinv[row], fp16
__device__ __half g_xh[(size_t)N_PAD * D];   // activations, fp16 (pad rows 0)
__device__ __half g_w16[3 * D * D];          // weights, fp16
__device__ float  g_dinv[N_NODES];
__device__ int    g_is64;
__device__ unsigned g_epack[N_EDGES];        // (col<<15) | slot
__device__ int    g_cnt[N_NODES];
__device__ int    g_rowptr[N_NODES + 1];
__device__ int    g_src[N_EDGES];
__device__ int    g_bsum[N_SCAN_BLOCKS];

// ===========================================================================
// Setup (merged kernels)
// ===========================================================================

// zero cnt everywhere; block 0 additionally detects edge dtype
__global__ void k_detect_zero(const unsigned int* __restrict__ buf) {
    int i = blockIdx.x * blockDim.x + threadIdx.x;
    if (i < N_NODES) g_cnt[i] = 0;
    if (blockIdx.x == 0) {
        __shared__ unsigned int acc;
        if (threadIdx.x == 0) acc = 0u;
        __syncthreads();
        unsigned int local = 0u;
        for (int k = threadIdx.x; k < 4096; k += blockDim.x)
            local |= buf[2 * k + 1];
        atomicOr(&acc, local);
        __syncthreads();
        if (threadIdx.x == 0) g_is64 = (acc == 0u) ? 1 : 0;
    }
}

// histogram target degree; the atomic return value doubles as the CSR slot
__global__ void k_hist_pack(const void* __restrict__ buf) {
    int e = blockIdx.x * blockDim.x + threadIdx.x;
    if (e >= N_EDGES) return;
    int c;
    if (g_is64) c = (int)((const long long*)buf)[e + N_EDGES];
    else        c = ((const int*)buf)[e + N_EDGES];
    int pos = atomicAdd(&g_cnt[c], 1);
    g_epack[e] = ((unsigned)c << 15) | ((unsigned)pos & 0x7FFFu);
}

// block-level exclusive scan of degrees; also dinv = rsqrt(1+deg)
__global__ void __launch_bounds__(SCAN_B)
k_scan1() {
    __shared__ int s[SCAN_B];
    int i = blockIdx.x * SCAN_B + threadIdx.x;
    int v = (i < N_NODES) ? g_cnt[i] : 0;
    if (i < N_NODES) g_dinv[i] = rsqrtf(1.0f + (float)v);
    s[threadIdx.x] = v;
    __syncthreads();
#pragma unroll
    for (int off = 1; off < SCAN_B; off <<= 1) {
        int t = (threadIdx.x >= off) ? s[threadIdx.x - off] : 0;
        __syncthreads();
        s[threadIdx.x] += t;
        __syncthreads();
    }
    if (i < N_NODES) g_rowptr[i] = s[threadIdx.x] - v;
    if (threadIdx.x == SCAN_B - 1) g_bsum[blockIdx.x] = s[SCAN_B - 1];
}

// every block redundantly scans the 98 block sums, then applies to its nodes
__global__ void k_scan23() {
    __shared__ int s[128];
    __shared__ int ex[128];
    int t = threadIdx.x;
    int v = 0;
    if (t < 128) {
        v = (t < N_SCAN_BLOCKS) ? g_bsum[t] : 0;
        s[t] = v;
    }
    __syncthreads();
#pragma unroll
    for (int off = 1; off < 128; off <<= 1) {
        int tv = 0;
        if (t < 128 && t >= off) tv = s[t - off];
        __syncthreads();
        if (t < 128) s[t] += tv;
        __syncthreads();
    }
    if (t < 128) ex[t] = s[t] - v;   // exclusive
    __syncthreads();
    int i = blockIdx.x * blockDim.x + t;
    if (i < N_NODES) g_rowptr[i] += ex[i >> 10];
    if (i == 0) g_rowptr[N_NODES] = N_EDGES;
}

// atomic-free CSR fill using the packed (col, slot)
__global__ void k_fill(const void* __restrict__ buf) {
    int e = blockIdx.x * blockDim.x + threadIdx.x;
    if (e >= N_EDGES) return;
    unsigned p = g_epack[e];
    int c = (int)(p >> 15);
    int pos = (int)(p & 0x7FFFu);
    int r;
    if (g_is64) r = (int)((const long long*)buf)[e];
    else        r = ((const int*)buf)[e];
    int idx = g_rowptr[c] + pos;
    if (idx < N_EDGES) g_src[idx] = r;
}

// W -> fp16
__global__ void k_w2h(const float* __restrict__ Ws) {
    int i = blockIdx.x * blockDim.x + threadIdx.x;
    if (i < 3 * D * D) g_w16[i] = __float2half_rn(Ws[i]);
}

// ===========================================================================
// fp16 wmma GEMM: block = 128x128 tile, 8 warps (4M x 2N), warp 32x64.
// LDM = 136 halfs (272B stride): conflict-free LDSM. fp32 accumulate.
// Layer 0 reads fp32 emb directly (converts in the fill).
// Epilogue stages through the dead A-tile smem; hs = (A@W)*dinv as fp16.
// ===========================================================================
#define LDH 136
#define GEMM_SMEM (2 * 128 * LDH * 2)      // A + W tiles, 69632 B

template<bool FROM_EMB>
__global__ void __launch_bounds__(256, 2)
k_gemm(const __half* __restrict__ Wl, const float* __restrict__ emb) {
    extern __shared__ __half smh[];
    __half* As = smh;                 // [128][LDH]
    __half* Wsm = smh + 128 * LDH;    // [128][LDH]

    const int tid = threadIdx.x;
    const int wid = tid >> 5;
    const int lane = tid & 31;
    const int wm = wid >> 1;          // 0..3 -> 32-row strip
    const int wn = wid & 1;           // 0..1 -> 64-col strip
    const int row0 = blockIdx.x * 128;

    // Fill W tile
    for (int idx = tid; idx < 2048; idx += 256) {
        int r = idx >> 4, c8 = idx & 15;
        uint4 v = ((const uint4*)(Wl + r * D))[c8];
        *(uint4*)(Wsm + r * LDH + c8 * 8) = v;
    }
    // Fill A tile
    for (int idx = tid; idx < 2048; idx += 256) {
        int r = idx >> 4, c8 = idx & 15;
        int row = row0 + r;
        uint4 v = make_uint4(0u, 0u, 0u, 0u);
        if (row < N_NODES) {
            if (FROM_EMB) {
                const float4* s = (const float4*)(emb + (size_t)row * D) + c8 * 2;
                float4 v0 = s[0], v1 = s[1];
                __half2 h;
                h = __floats2half2_rn(v0.x, v0.y); v.x = *(uint32_t*)&h;
                h = __floats2half2_rn(v0.z, v0.w); v.y = *(uint32_t*)&h;
                h = __floats2half2_rn(v1.x, v1.y); v.z = *(uint32_t*)&h;
                h = __floats2half2_rn(v1.z, v1.w); v.w = *(uint32_t*)&h;
            } else {
                v = ((const uint4*)(g_xh + (size_t)row * D))[c8];
            }
        }
        *(uint4*)(As + r * LDH + c8 * 8) = v;
    }
    __syncthreads();

    wmma::fragment<wmma::accumulator, 16, 16, 16, float> acc[2][4];
#pragma unroll
    for (int i = 0; i < 2; i++)
#pragma unroll
        for (int j = 0; j < 4; j++) wmma::fill_fragment(acc[i][j], 0.0f);

#pragma unroll
    for (int k = 0; k < 8; k++) {
        wmma::fragment<wmma::matrix_a, 16, 16, 16, __half, wmma::row_major> a[2];
        wmma::fragment<wmma::matrix_b, 16, 16, 16, __half, wmma::row_major> b[4];
#pragma unroll
        for (int i = 0; i < 2; i++)
            wmma::load_matrix_sync(a[i], As + (wm * 32 + i * 16) * LDH + k * 16,
                                   LDH);
#pragma unroll
        for (int j = 0; j < 4; j++)
            wmma::load_matrix_sync(b[j], Wsm + (k * 16) * LDH + wn * 64 + j * 16,
                                   LDH);
#pragma unroll
        for (int i = 0; i < 2; i++)
#pragma unroll
            for (int j = 0; j < 4; j++)
                wmma::mma_sync(acc[i][j], a[i], b[j], acc[i][j]);
    }

    // A/W tiles are dead; stage epilogue strips in the A region.
    __syncthreads();
    float* stage = reinterpret_cast<float*>(smh) + wid * (16 * 68);
#pragma unroll
    for (int i = 0; i < 2; i++) {
#pragma unroll
        for (int j = 0; j < 4; j++)
            wmma::store_matrix_sync(stage + j * 16, acc[i][j], 68,
                                    wmma::mem_row_major);
        __syncwarp();
        int r = lane >> 1;                 // 0..15
        int ch = (lane & 1) * 32;          // 32-col half
        int row = row0 + wm * 32 + i * 16 + r;
        float s = (row < N_NODES) ? g_dinv[row] : 0.0f;
        const float* src = stage + r * 68 + ch;
        if (row < N_NODES) {
            uint4* dst = (uint4*)(g_hs + (size_t)row * D + wn * 64 + ch);
#pragma unroll
            for (int q = 0; q < 4; q++) {   // 4 x uint4 = 32 halves
                uint4 o;
                __half2 h;
                h = __floats2half2_rn(src[q * 8 + 0] * s, src[q * 8 + 1] * s);
                o.x = *(uint32_t*)&h;
                h = __floats2half2_rn(src[q * 8 + 2] * s, src[q * 8 + 3] * s);
                o.y = *(uint32_t*)&h;
                h = __floats2half2_rn(src[q * 8 + 4] * s, src[q * 8 + 5] * s);
                o.z = *(uint32_t*)&h;
                h = __floats2half2_rn(src[q * 8 + 6] * s, src[q * 8 + 7] * s);
                o.w = *(uint32_t*)&h;
                dst[q] = o;
            }
        }
        __syncwarp();
    }
}

// ===========================================================================
// Aggregation: one warp per target node, fp16 gather, fp32 accumulate.
// ===========================================================================
__global__ void __launch_bounds__(256)
k_aggregate(const float* __restrict__ bias, float* __restrict__ out,
            int use_out) {
    int node = (blockIdx.x * blockDim.x + threadIdx.x) >> 5;
    int lane = threadIdx.x & 31;
    if (node >= N_NODES) return;

    float dinv_c = g_dinv[node];
    const uint2* HS = (const uint2*)g_hs;   // 32 uint2 per row

    uint2 v = HS[(size_t)node * 32 + lane];
    float2 f0 = __half22float2(*(__half2*)&v.x);
    float2 f1 = __half22float2(*(__half2*)&v.y);
    float4 acc0 = make_float4(f0.x, f0.y, f1.x, f1.y);
    float4 acc1 = make_float4(0.f, 0.f, 0.f, 0.f);

    int beg = g_rowptr[node];
    int end = g_rowptr[node + 1];
    for (int base = beg; base < end; base += 32) {
        int j = base + lane;
        int r = (j < end) ? g_src[j] : 0;
        int cnt = min(32, end - base);
        int k = 0;
        for (; k + 1 < cnt; k += 2) {
            int r0 = __shfl_sync(0xffffffffu, r, k);
            int r1 = __shfl_sync(0xffffffffu, r, k + 1);
            uint2 v0 = HS[(size_t)r0 * 32 + lane];
            uint2 v1 = HS[(size_t)r1 * 32 + lane];
            float2 a0 = __half22float2(*(__half2*)&v0.x);
            float2 a1 = __half22float2(*(__half2*)&v0.y);
            float2 b0 = __half22float2(*(__half2*)&v1.x);
            float2 b1 = __half22float2(*(__half2*)&v1.y);
            acc0.x += a0.x; acc0.y += a0.y; acc0.z += a1.x; acc0.w += a1.y;
            acc1.x += b0.x; acc1.y += b0.y; acc1.z += b1.x; acc1.w += b1.y;
        }
        if (k < cnt) {
            int r0 = __shfl_sync(0xffffffffu, r, k);
            uint2 v0 = HS[(size_t)r0 * 32 + lane];
            float2 a0 = __half22float2(*(__half2*)&v0.x);
            float2 a1 = __half22float2(*(__half2*)&v0.y);
            acc0.x += a0.x; acc0.y += a0.y; acc0.z += a1.x; acc0.w += a1.y;
        }
    }

    float4 bb = ((const float4*)bias)[lane];
    float4 x;
    x.x = fmaxf(fmaf(dinv_c, acc0.x + acc1.x, bb.x), 0.f);
    x.y = fmaxf(fmaf(dinv_c, acc0.y + acc1.y, bb.y), 0.f);
    x.z = fmaxf(fmaf(dinv_c, acc0.z + acc1.z, bb.z), 0.f);
    x.w = fmaxf(fmaf(dinv_c, acc0.w + acc1.w, bb.w), 0.f);

    if (use_out) {
        ((float4*)(out + (size_t)node * D))[lane] = x;
    } else {
        uint2 o;
        __half2 h;
        h = __floats2half2_rn(x.x, x.y); o.x = *(uint32_t*)&h;
        h = __floats2half2_rn(x.z, x.w); o.y = *(uint32_t*)&h;
        ((uint2*)(g_xh + (size_t)node * D))[lane] = o;
    }
}

// ===========================================================================
// Launch
// ===========================================================================
extern "C" void kernel_launch(void* const* d_in, const int* in_sizes, int n_in,
                              void* d_out, int out_size) {
    const void* edge = d_in[0];
    const float* emb = (const float*)d_in[1];
    const float* Ws  = (const float*)d_in[2];
    const float* bs  = (const float*)d_in[3];
    float* out = (float*)d_out;

    __half* g_w16_p;
    cudaGetSymbolAddress((void**)&g_w16_p, g_w16);

    static bool attr_done = false;
    if (!attr_done) {
        cudaFuncSetAttribute(k_gemm<true>,
                             cudaFuncAttributeMaxDynamicSharedMemorySize, GEMM_SMEM);
        cudaFuncSetAttribute(k_gemm<false>,
                             cudaFuncAttributeMaxDynamicSharedMemorySize, GEMM_SMEM);
        attr_done = true;
    }

    const int nb_nodes = (N_NODES + 255) / 256;
    const int nb_edges = (N_EDGES + 255) / 256;

    k_detect_zero<<<nb_nodes, 256>>>((const unsigned int*)edge);
    k_w2h<<<(3 * D * D + 255) / 256, 256>>>(Ws);
    k_hist_pack<<<nb_edges, 256>>>(edge);
    k_scan1<<<N_SCAN_BLOCKS, SCAN_B>>>();
    k_scan23<<<nb_nodes, 256>>>();
    k_fill<<<nb_edges, 256>>>(edge);

    const int gemm_blocks = N_PAD / 128;                 // 782
    const int agg_blocks = (N_NODES * 32 + 255) / 256;   // 12500

    // Layer 0 (reads emb fp32 directly)
    k_gemm<true><<<gemm_blocks, 256, GEMM_SMEM>>>(g_w16_p + 0 * D * D, emb);
    k_aggregate<<<agg_blocks, 256>>>(bs + 0 * D, out, 0);
    // Layer 1
    k_gemm<false><<<gemm_blocks, 256, GEMM_SMEM>>>(g_w16_p + 1 * D * D, nullptr);
    k_aggregate<<<agg_blocks, 256>>>(bs + 1 * D, out, 0);
    // Layer 2 -> d_out (ReLU in aggregate)
    k_gemm<false><<<gemm_blocks, 256, GEMM_SMEM>>>(g_w16_p + 2 * D * D, nullptr);
    k_aggregate<<<agg_blocks, 256>>>(bs + 2 * D, out, 1);
}